// round 14
// baseline (speedup 1.0000x reference)
#include <cuda_runtime.h>
#include <math_constants.h>
#include <cstdint>

#define BATCH 16
#define SEQ   4096
#define RANKS 8
#define PER   512
#define NTC   512
#define NEG   (-CUDART_INF_F)

__device__ __forceinline__ void st_remote_f32(float* lp, unsigned int r, float v) {
    unsigned int la = (unsigned int)__cvta_generic_to_shared((void*)lp);
    unsigned int ra;
    asm("mapa.shared::cluster.u32 %0, %1, %2;" : "=r"(ra) : "r"(la), "r"(r));
    asm volatile("st.shared::cluster.f32 [%0], %1;" :: "r"(ra), "f"(v) : "memory");
}
__device__ __forceinline__ void st_remote_s32(int* lp, unsigned int r, int v) {
    unsigned int la = (unsigned int)__cvta_generic_to_shared((void*)lp);
    unsigned int ra;
    asm("mapa.shared::cluster.u32 %0, %1, %2;" : "=r"(ra) : "r"(la), "r"(r));
    asm volatile("st.shared::cluster.b32 [%0], %1;" :: "r"(ra), "r"(v) : "memory");
}
// release-arrive on rank r's mbarrier: publishes THIS thread's prior remote stores
__device__ __forceinline__ void mbar_arrive_remote_rel(unsigned long long* lp, unsigned int r) {
    unsigned int la = (unsigned int)__cvta_generic_to_shared((void*)lp);
    unsigned int ra;
    asm("mapa.shared::cluster.u32 %0, %1, %2;" : "=r"(ra) : "r"(la), "r"(r));
    asm volatile("mbarrier.arrive.release.cluster.shared::cluster.b64 _, [%0];" :: "r"(ra) : "memory");
}
__device__ __forceinline__ void mbar_wait_acq(unsigned long long* lp, unsigned int parity) {
    unsigned int la = (unsigned int)__cvta_generic_to_shared((void*)lp);
    asm volatile(
        "{\n\t.reg .pred P;\n"
        "WAITLOOP_%=:\n\t"
        "mbarrier.try_wait.parity.acquire.cluster.shared::cta.b64 P, [%0], %1;\n\t"
        "@!P bra WAITLOOP_%=;\n\t}"
        :: "r"(la), "r"(parity) : "memory");
}
#define CLUSTER_SYNC() do { \
    asm volatile("barrier.cluster.arrive.aligned;" ::: "memory"); \
    asm volatile("barrier.cluster.wait.aligned;"   ::: "memory"); } while (0)

__global__ __launch_bounds__(NTC, 1) __cluster_dims__(RANKS, 1, 1)
void pred_head_mb2(const float* __restrict__ start_logits,
                   const float* __restrict__ end_logits,
                   float* __restrict__ out) {
    __shared__ float pfx_e[544];   // [0..511] own end-logit prefix; [512..541] next-chunk halo
    __shared__ float sfx_s[544];   // [32..543] own start-logit suffix; [2..31] prev-chunk halo
    __shared__ float redS[16], redE[16];
    __shared__ float wav[16], wav2[16];
    __shared__ int   wai[16], wai2[16];
    __shared__ float s_parts[RANKS], e_parts[RANKS];
    __shared__ float wsv[RANKS], wev[RANKS];
    __shared__ int   wsi[RANKS], wei[RANKS];
    __shared__ unsigned long long mbar;

    const int t = threadIdx.x;
    const int lane = t & 31;
    const int wid  = t >> 5;
    unsigned int rank;
    asm("mov.u32 %0, %%cluster_ctarank;" : "=r"(rank));
    const int row = blockIdx.x >> 3;
    const int col = (int)rank * PER + t;
    const float* srow = start_logits + row * SEQ;
    const float* erow = end_logits   + row * SEQ;

    // ---- own mbarrier init: rank0 expects 32 arrivals (4/CTA), others 16 (2/CTA) ----
    if (t == 0) {
        unsigned int la = (unsigned int)__cvta_generic_to_shared(&mbar);
        unsigned int cnt = (rank == 0) ? 4 * RANKS : 2 * RANKS;
        asm volatile("mbarrier.init.shared.b64 [%0], %1;" :: "r"(la), "r"(cnt) : "memory");
    }

    // ---- all global loads first; top cluster.sync hides under their latency ----
    const float sl = srow[col];
    const float el = erow[col];
    float hv = 0.f;
    if (wid == 1 && lane < 30)
        hv = (rank > 0) ? srow[(int)rank * PER - 30 + lane] : NEG;
    if (wid == 2 && lane < 30)
        hv = (rank < RANKS - 1) ? erow[((int)rank + 1) * PER + lane] : NEG;

    CLUSTER_SYNC();   // mbar-init visibility only; overlapped with LDGs

    // ---- halo scans (log space) ----
    if (wid == 1 && lane < 30) {
        #pragma unroll
        for (int o = 1; o < 32; o <<= 1) {
            float b = __shfl_down_sync(0x3fffffffu, hv, o);
            if (lane + o < 30) hv = fmaxf(hv, b);
        }
        sfx_s[2 + lane] = hv;      // prev-chunk suffix of start-logit
    }
    if (wid == 2 && lane < 30) {
        #pragma unroll
        for (int o = 1; o < 32; o <<= 1) {
            float a = __shfl_up_sync(0x3fffffffu, hv, o);
            if (lane >= o) hv = fmaxf(hv, a);
        }
        pfx_e[512 + lane] = hv;    // next-chunk prefix of end-logit
    }

    // ---- per-warp prefix/suffix maxima on logits ----
    float pe = el, se_ = el;
    float ps_ = sl, ssx = sl;
    #pragma unroll
    for (int o = 1; o < 32; o <<= 1) {
        float a = __shfl_up_sync(0xffffffffu, pe, o);    if (lane >= o)     pe  = fmaxf(pe, a);
        float b = __shfl_down_sync(0xffffffffu, se_, o); if (lane + o < 32) se_ = fmaxf(se_, b);
        float c = __shfl_up_sync(0xffffffffu, ps_, o);   if (lane >= o)     ps_ = fmaxf(ps_, c);
        float d = __shfl_down_sync(0xffffffffu, ssx, o); if (lane + o < 32) ssx = fmaxf(ssx, d);
    }
    pfx_e[t] = pe;
    sfx_s[32 + t] = ssx;

    // ---- exps (MUFU, off the argmax chain) + per-warp partial sums ----
    const float sv = __expf(sl);
    const float ev = __expf(el);
    float a = sv, c = ev;
    #pragma unroll
    for (int o = 16; o; o >>= 1) {
        a += __shfl_xor_sync(0xffffffffu, a, o);
        c += __shfl_xor_sync(0xffffffffu, c, o);
    }
    if (lane == 0) { redS[wid] = a; redE[wid] = c; }

    __syncthreads();   // bar1: scans + halos + sum partials visible

    // ---- width-31 windows via prefix/suffix decomposition (log space) ----
    const float pe30 = __shfl_sync(0xffffffffu, pe, 30);
    const float ss1  = __shfl_sync(0xffffffffu, ssx, 1);
    float F, Bv;
    if (lane == 0)       F = pe30;
    else if (lane == 1)  F = se_;
    else                 F = fmaxf(se_, pfx_e[t + 30]);
    if (lane == 31)      Bv = ss1;
    else if (lane == 30) Bv = ps_;
    else                 Bv = fmaxf(ps_, sfx_s[t + 2]);

    // ---- log-space scores + warp argmax (dual, first-index tie-break) ----
    float bsv = sl + F;  int bsi = col;
    float bev = el + Bv; int bei = col;
    #pragma unroll
    for (int o = 16; o; o >>= 1) {
        float ov = __shfl_xor_sync(0xffffffffu, bsv, o);
        int   oi = __shfl_xor_sync(0xffffffffu, bsi, o);
        if (ov > bsv || (ov == bsv && oi < bsi)) { bsv = ov; bsi = oi; }
        float ov2 = __shfl_xor_sync(0xffffffffu, bev, o);
        int   oi2 = __shfl_xor_sync(0xffffffffu, bei, o);
        if (ov2 > bev || (ov2 == bev && oi2 < bei)) { bev = ov2; bei = oi2; }
    }
    if (lane == 0) { wav[wid] = bsv; wai[wid] = bsi; wav2[wid] = bev; wai2[wid] = bei; }

    __syncthreads();   // bar2: warp partials visible

    // ---- pushes + per-thread release-arrives (no cluster.sync) ----
    if (wid == 0) {
        float v1 = (lane < 16) ? redS[lane] : 0.f;
        float v2 = (lane < 16) ? redE[lane] : 0.f;
        #pragma unroll
        for (int o = 8; o; o >>= 1) {
            v1 += __shfl_xor_sync(0xffffffffu, v1, o);
            v2 += __shfl_xor_sync(0xffffffffu, v2, o);
        }
        if (lane < 8) {               // ship start-sum to rank 'lane'
            st_remote_f32(&s_parts[rank], (unsigned int)lane, v1);
            mbar_arrive_remote_rel(&mbar, (unsigned int)lane);
        } else if (lane < 16) {       // ship end-sum to rank 'lane-8'
            st_remote_f32(&e_parts[rank], (unsigned int)(lane - 8), v2);
            mbar_arrive_remote_rel(&mbar, (unsigned int)(lane - 8));
        }
    } else if (wid == 1) {
        float v1 = (lane < 16) ? wav[lane] : NEG;
        int   i1 = (lane < 16) ? wai[lane] : 0x7fffffff;
        #pragma unroll
        for (int o = 8; o; o >>= 1) {
            float ov = __shfl_xor_sync(0xffffffffu, v1, o);
            int   oi = __shfl_xor_sync(0xffffffffu, i1, o);
            if (ov > v1 || (ov == v1 && oi < i1)) { v1 = ov; i1 = oi; }
        }
        if (lane == 0) {
            st_remote_f32(&wsv[rank], 0u, v1);
            st_remote_s32(&wsi[rank], 0u, i1);
            mbar_arrive_remote_rel(&mbar, 0u);
        }
    } else if (wid == 2) {
        float v2 = (lane < 16) ? wav2[lane] : NEG;
        int   i2 = (lane < 16) ? wai2[lane] : 0x7fffffff;
        #pragma unroll
        for (int o = 8; o; o >>= 1) {
            float ov = __shfl_xor_sync(0xffffffffu, v2, o);
            int   oi = __shfl_xor_sync(0xffffffffu, i2, o);
            if (ov > v2 || (ov == v2 && oi < i2)) { v2 = ov; i2 = oi; }
        }
        if (lane == 0) {
            st_remote_f32(&wev[rank], 0u, v2);
            st_remote_s32(&wei[rank], 0u, i2);
            mbar_arrive_remote_rel(&mbar, 0u);
        }
    }

    // ---- wait on OWN mbarrier only (cheap wakeup; no cluster barrier, no L1 flush) ----
    mbar_wait_acq(&mbar, 0u);

    // ---- probs: every warp folds the 8+8 partials; STG ----
    {
        float v = (lane < 8) ? s_parts[lane] : ((lane < 16) ? e_parts[lane - 8] : 0.f);
        v += __shfl_xor_sync(0xffffffffu, v, 4);
        v += __shfl_xor_sync(0xffffffffu, v, 2);
        v += __shfl_xor_sync(0xffffffffu, v, 1);
        const float inv_s = __frcp_rn(__shfl_sync(0xffffffffu, v, 0));
        const float inv_e = __frcp_rn(__shfl_sync(0xffffffffu, v, 8));
        out[row * SEQ + col]               = sv * inv_s;
        out[BATCH * SEQ + row * SEQ + col] = ev * inv_e;
    }

    // ---- rank 0 reduces the 8 winners (all pushed pre-arrive, visible via acquire) ----
    if (rank == 0 && wid == 1) {
        float v1 = (lane < 8) ? wsv[lane] : NEG;
        int   i1 = (lane < 8) ? wsi[lane] : 0x7fffffff;
        float v2 = (lane < 8) ? wev[lane] : NEG;
        int   i2 = (lane < 8) ? wei[lane] : 0x7fffffff;
        #pragma unroll
        for (int o = 4; o; o >>= 1) {
            float ov = __shfl_xor_sync(0xffffffffu, v1, o);
            int   oi = __shfl_xor_sync(0xffffffffu, i1, o);
            if (ov > v1 || (ov == v1 && oi < i1)) { v1 = ov; i1 = oi; }
            float ov2 = __shfl_xor_sync(0xffffffffu, v2, o);
            int   oi2 = __shfl_xor_sync(0xffffffffu, i2, o);
            if (ov2 > v2 || (ov2 == v2 && oi2 < i2)) { v2 = ov2; i2 = oi2; }
        }
        if (lane == 0) {
            out[2 * BATCH * SEQ + row]         = (float)v1, out[2 * BATCH * SEQ + row] = (float)i1;
            out[2 * BATCH * SEQ + BATCH + row] = (float)i2;
        }
    }
}

extern "C" void kernel_launch(void* const* d_in, const int* in_sizes, int n_in,
                              void* d_out, int out_size) {
    const float* start_logits = (const float*)d_in[0];
    const float* end_logits   = (const float*)d_in[1];
    float* out = (float*)d_out;
    pred_head_mb2<<<BATCH * RANKS, NTC>>>(start_logits, end_logits, out);
}